// round 12
// baseline (speedup 1.0000x reference)
#include <cuda_runtime.h>

// JaggedConv2D: per-channel depthwise conv, ragged odd kernels 5..29 centered
// in 29x29 window, SAME padding. B=4, C=128, H=W=256, fp32.
//
// R12 (base: R11, 359us): halve smem crossbar traffic.
//  - RX=16, RY=1: each thread computes 1 row x 16 cols -> 2x vin reuse
//  - full-row vin load per ky (12 LDS.128 @K=29), 4-tap weight float4
//    broadcasts -> ~56 wf vs 116 FFMA cyc/SMSP (was ~112)
//  - lane<->row mapping, SW/4 odd -> all LDS.128 conflict-free (4-wf floor)
//  - fill epoch unchanged from R11 (vectorized, divide-free, MLP=4)
//  - accumulation order (ky outer, kx sequential) identical -> bit-identical

#define BB 4
#define CC 128
#define HH 256
#define WW 256
#define KMAXSZ 29

#define TW 64
#define TH 64
#define RX 16
#define NTH 256

#define WSTRIDE 32
#define WT_OFF  (WSTRIDE * KMAXSZ)   // 928 floats (128B aligned)

template<int K>
__device__ __forceinline__ void conv_body(const float* __restrict__ x,
                                          const float* __restrict__ kern,
                                          float* __restrict__ out,
                                          int ch, int b, float* smem)
{
    constexpr int HALO  = K / 2;
    constexpr int HALO4 = (HALO + 3) & ~3;   // 4-aligned left halo
    constexpr int D     = HALO4 - HALO;      // column shift (0..3)
    constexpr int OFF   = D;                 // register shift (base is aligned)
    constexpr int IH    = TH + K - 1;
    constexpr int IW    = TW + K - 1 + D;
    constexpr int NVC   = (OFF + K - 1 + RX - 1) / 4 + 1;   // vin float4 count
    constexpr int NG    = (K + 3) / 4;                      // 4-tap weight groups
    constexpr int REACH = (TW - RX) + 4 * NVC;
    constexpr int SW0   = (((IW > REACH) ? IW : REACH) + 3) & ~3;
    constexpr int SW    = ((SW0 >> 2) & 1) ? SW0 : SW0 + 4;  // SW/4 odd
    constexpr int SW4   = SW / 4;
    constexpr int S     = (KMAXSZ - K) / 2;

    float* sWt = smem;            // [K][WSTRIDE]
    float* sIn = smem + WT_OFF;   // [IH][SW], base 128B aligned

    const int tid = threadIdx.x;
    const int tileX0 = blockIdx.x * TW;
    const int tileY0 = blockIdx.y * TH;

    // ---- weights: ragged KxK window -> stride-32 rows, zero padded ----
    const float* kbase = kern + (size_t)ch * KMAXSZ * KMAXSZ;
    #pragma unroll 1
    for (int i = tid; i < K * WSTRIDE; i += NTH) {
        int ky = i >> 5, kx = i & 31;
        float v = 0.0f;
        if (kx < K)
            v = kbase[(S + ky) * KMAXSZ + (S + kx)];
        sWt[i] = v;
    }

    // ---- input tile (+halo), vectorized row fill, zero padded ----
    // smem col c holds global x = tileX0 - HALO4 + c (4-aligned origin)
    {
        const float* xbase = x + (size_t)(b * CC + ch) * HH * WW;
        const int inY0 = tileY0 - HALO;
        const int inX0 = tileX0 - HALO4;
        const int lane = tid & 31;
        const int warp = tid >> 5;

        if (lane < SW4) {
            const int gx0 = inX0 + lane * 4;                 // 4-aligned
            const bool xfast = (gx0 >= 0) && (gx0 + 4 <= WW);
            #pragma unroll 1
            for (int rb = warp; rb < IH; rb += 32) {
                float4 v[4];
                #pragma unroll
                for (int u = 0; u < 4; u++) {
                    int r = rb + 8 * u;
                    v[u].x = 0.f; v[u].y = 0.f; v[u].z = 0.f; v[u].w = 0.f;
                    int gy = inY0 + r;
                    if (r < IH && (unsigned)gy < (unsigned)HH) {
                        const float* gp = xbase + (size_t)gy * WW + gx0;
                        if (xfast) {
                            v[u] = *reinterpret_cast<const float4*>(gp);
                        } else {
                            if ((unsigned)(gx0 + 0) < (unsigned)WW) v[u].x = gp[0];
                            if ((unsigned)(gx0 + 1) < (unsigned)WW) v[u].y = gp[1];
                            if ((unsigned)(gx0 + 2) < (unsigned)WW) v[u].z = gp[2];
                            if ((unsigned)(gx0 + 3) < (unsigned)WW) v[u].w = gp[3];
                        }
                    }
                }
                #pragma unroll
                for (int u = 0; u < 4; u++) {
                    int r = rb + 8 * u;
                    if (r < IH)
                        *reinterpret_cast<float4*>(&sIn[r * SW + lane * 4]) = v[u];
                }
            }
        }
    }
    __syncthreads();

    // ---- lane<->row mapping: warp w -> tx=w&3, rows (w>>2)*32 + lane ----
    // quarter-warp = 8 consecutive rows, same tx; SW/4 odd -> r*(SW/4) mod 8
    // covers all 8 bank groups -> conflict-free LDS.128
    const int lane = tid & 31;
    const int warp = tid >> 5;
    const int tx   = warp & 3;
    const int row  = (warp >> 2) * 32 + lane;
    const int c0   = tx * RX;                // 64B aligned

    float acc[RX];
    #pragma unroll
    for (int j = 0; j < RX; j++)
        acc[j] = 0.0f;

    #pragma unroll 1
    for (int ky = 0; ky < K; ky++) {
        // full-row input window: NVC aligned float4 loads
        const float* rp = &sIn[(row + ky) * SW + c0];   // 16B aligned
        float vin[NVC * 4];
        #pragma unroll
        for (int t = 0; t < NVC; t++) {
            float4 q = *reinterpret_cast<const float4*>(rp + 4 * t);
            vin[4*t+0] = q.x; vin[4*t+1] = q.y;
            vin[4*t+2] = q.z; vin[4*t+3] = q.w;
        }

        const float* wr = &sWt[ky * WSTRIDE];
        #pragma unroll
        for (int g = 0; g < NG; g++) {
            float4 wq = *reinterpret_cast<const float4*>(wr + 4 * g);  // broadcast
            float w4[4] = {wq.x, wq.y, wq.z, wq.w};
            #pragma unroll
            for (int t = 0; t < 4; t++) {
                if (4 * g + t < K) {
                    #pragma unroll
                    for (int j = 0; j < RX; j++)
                        acc[j] = fmaf(w4[t], vin[OFF + 4 * g + t + j], acc[j]);
                }
            }
        }
    }

    // ---- store: 4 float4, one row per thread ----
    float* op = out + (size_t)(b * CC + ch) * HH * WW
              + (size_t)(tileY0 + row) * WW + tileX0 + c0;
    #pragma unroll
    for (int t = 0; t < 4; t++) {
        float4 v;
        v.x = acc[4*t+0]; v.y = acc[4*t+1]; v.z = acc[4*t+2]; v.w = acc[4*t+3];
        *reinterpret_cast<float4*>(op + 4 * t) = v;
    }
}

__global__ __launch_bounds__(NTH, 3)
void jagged_conv(const float* __restrict__ x,
                 const float* __restrict__ kern,
                 float* __restrict__ out)
{
    extern __shared__ float smem[];
    const int z  = blockIdx.z;
    const int ch = (CC - 1) - (z >> 2);   // descending K: big kernels first
    const int b  = z & 3;

    // k_i = floor(5 + 24*i/127), forced odd (matches np.linspace/astype)
    int k = 5 + (24 * ch) / 127;
    if ((k & 1) == 0) k -= 1;

    switch (k) {
        case  5: conv_body< 5>(x, kern, out, ch, b, smem); break;
        case  7: conv_body< 7>(x, kern, out, ch, b, smem); break;
        case  9: conv_body< 9>(x, kern, out, ch, b, smem); break;
        case 11: conv_body<11>(x, kern, out, ch, b, smem); break;
        case 13: conv_body<13>(x, kern, out, ch, b, smem); break;
        case 15: conv_body<15>(x, kern, out, ch, b, smem); break;
        case 17: conv_body<17>(x, kern, out, ch, b, smem); break;
        case 19: conv_body<19>(x, kern, out, ch, b, smem); break;
        case 21: conv_body<21>(x, kern, out, ch, b, smem); break;
        case 23: conv_body<23>(x, kern, out, ch, b, smem); break;
        case 25: conv_body<25>(x, kern, out, ch, b, smem); break;
        case 27: conv_body<27>(x, kern, out, ch, b, smem); break;
        case 29: conv_body<29>(x, kern, out, ch, b, smem); break;
        default: break;
    }
}

extern "C" void kernel_launch(void* const* d_in, const int* in_sizes, int n_in,
                              void* d_out, int out_size)
{
    (void)in_sizes; (void)n_in; (void)out_size;
    const float* x    = (const float*)d_in[0];
    const float* kern = (const float*)d_in[1];
    float* out        = (float*)d_out;

    // max smem across K: K=29 -> WT_OFF(928) + IH(92)*SW(100) = 10128 floats
    const int smem_bytes = (WT_OFF + 92 * 100) * (int)sizeof(float);
    cudaFuncSetAttribute(jagged_conv,
                         cudaFuncAttributeMaxDynamicSharedMemorySize, smem_bytes);

    dim3 grid(WW / TW, HH / TH, BB * CC);
    dim3 block(NTH, 1, 1);
    jagged_conv<<<grid, block, smem_bytes>>>(x, kern, out);
}